// round 14
// baseline (speedup 1.0000x reference)
#include <cuda_runtime.h>
#include <cuda_fp16.h>

#define N0C 100000
#define N1C 100000

#define KV_BLOCKS ((N0C + 255) / 256)   // 391
#define Q_BLOCKS  ((N1C + 255) / 256)   // 391

// KV smem: Ws(67*96) + Bs(96) + Xs(67*136) floats = 15640 f = 62.56 KB (dynamic)
#define KV_SMEM_FLOATS (67 * 96 + 96 + 67 * 136)

// Packed-f32x2 helpers (Blackwell FFMA2 path, PTX-only)
#define FFMA2(d, a, b, c) \
    asm("fma.rn.f32x2 %0, %1, %2, %3;" : "=l"(d) : "l"(a), "l"(b), "l"(c))
__device__ __forceinline__ unsigned long long pack2(float lo, float hi) {
    unsigned long long r;
    asm("mov.b64 %0, {%1, %2};" : "=l"(r) : "f"(lo), "f"(hi));
    return r;
}
__device__ __forceinline__ float2 unpack2(unsigned long long v) {
    float2 r;
    asm("mov.b64 {%0, %1}, %2;" : "=f"(r.x), "=f"(r.y) : "l"(v));
    return r;
}

// KV0 in fp16, padded rows of 128 halves (256B, line-aligned):
//   halves [0,32)   : K part   halves [64,128) : V part
__device__ __half g_KVh[(size_t)N0C * 128];
__device__ float  g_Q[(size_t)N1C * 32];

// ---------------------------------------------------------------------------
// Q projection: [N1,64] x [64,32]. Block 256 thr, 2 passes x 128 points.
// Warp = 32 pts x 16 cols; thread = 4 pts x 4 cols. x-load shared across
// col-groups: 1 LDS.128 wavefront per warp-iter.
// ---------------------------------------------------------------------------
__global__ __launch_bounds__(256) void q_prep(
    const float* __restrict__ feats1,
    const float* __restrict__ Wq, const float* __restrict__ bq)
{
    __shared__ __align__(16) float smem[64 * 32 + 32 + 64 * 136];  // 43.1 KB
    float (*Ws)[32]  = (float (*)[32])smem;
    float* Bs        = smem + 64 * 32;
    float (*Xs)[136] = (float (*)[136])(smem + 64 * 32 + 32);

    const int t = threadIdx.x;

    const float4* Wq4 = (const float4*)Wq;
    for (int idx = t; idx < 512; idx += 256)
        ((float4*)Ws)[idx] = Wq4[idx];
    if (t < 32) Bs[t] = bq[t];

    const int w  = t >> 5, l = t & 31;
    const int p0 = (w >> 1) * 32 + (l & 7) * 4;   // 4 slices of 32 pts
    const int c0 = (w & 1) * 16 + (l >> 3) * 4;   // 2 col halves, 4 col groups

    const int base0 = blockIdx.x * 256;
#pragma unroll 1
    for (int pass = 0; pass < 2; pass++) {
        const int base = base0 + pass * 128;

        for (int idx = t; idx < 128 * 64; idx += 256) {
            int p = idx >> 6, i = idx & 63;
            int pt = base + p;
            Xs[i][p] = (pt < N1C) ? feats1[(size_t)pt * 64 + i] : 0.0f;
        }
        __syncthreads();

        unsigned long long acc[4][2];
        {
            unsigned long long b0 = pack2(Bs[c0], Bs[c0 + 1]);
            unsigned long long b1 = pack2(Bs[c0 + 2], Bs[c0 + 3]);
#pragma unroll
            for (int pp = 0; pp < 4; pp++) { acc[pp][0] = b0; acc[pp][1] = b1; }
        }

#pragma unroll 8
        for (int i = 0; i < 64; i++) {
            const float4 xv = *(const float4*)&Xs[i][p0];
            const unsigned long long* wr = (const unsigned long long*)&Ws[i][c0];
            const unsigned long long w0 = wr[0], w1 = wr[1];
            unsigned long long xx[4];
            xx[0] = pack2(xv.x, xv.x); xx[1] = pack2(xv.y, xv.y);
            xx[2] = pack2(xv.z, xv.z); xx[3] = pack2(xv.w, xv.w);
#pragma unroll
            for (int pp = 0; pp < 4; pp++) {
                FFMA2(acc[pp][0], xx[pp], w0, acc[pp][0]);
                FFMA2(acc[pp][1], xx[pp], w1, acc[pp][1]);
            }
        }

#pragma unroll
        for (int pp = 0; pp < 4; pp++) {
            int pt = base + p0 + pp;
            if (pt < N1C) {
                float2 v0 = unpack2(acc[pp][0]);
                float2 v1 = unpack2(acc[pp][1]);
                *(float4*)(g_Q + (size_t)pt * 32 + c0) = make_float4(v0.x, v0.y, v1.x, v1.y);
            }
        }
        __syncthreads();
    }
}

// ---------------------------------------------------------------------------
// KV projection: [N0,67] x [67,96]. Block 256 thr, 2 passes x 128 points.
// Warp = 32 pts x 48 cols; thread = 4 pts x 12 cols.
// ---------------------------------------------------------------------------
__global__ __launch_bounds__(256) void kv_prep(
    const float* __restrict__ feats0, const float* __restrict__ coords0,
    const float* __restrict__ Wk, const float* __restrict__ bk,
    const float* __restrict__ Wv, const float* __restrict__ bv)
{
    extern __shared__ __align__(16) float smem[];
    float (*Ws)[96]  = (float (*)[96])smem;                 // [67][96]
    float* Bs        = smem + 67 * 96;                      // [96]
    float (*Xs)[136] = (float (*)[136])(smem + 67 * 96 + 96); // [67][128+8]

    const int t = threadIdx.x;

    const float4* Wk4 = (const float4*)Wk;   // 67 x 8
    const float4* Wv4 = (const float4*)Wv;   // 67 x 16
    for (int idx = t; idx < 67 * 24; idx += 256) {
        int i = idx / 24, c4 = idx % 24;
        float4 v = (c4 < 8) ? Wk4[i * 8 + c4] : Wv4[i * 16 + (c4 - 8)];
        *(float4*)&Ws[i][c4 * 4] = v;
    }
    if (t < 96) Bs[t] = (t < 32) ? bk[t] : bv[t - 32];

    const int w  = t >> 5, l = t & 31;
    const int p0 = (w >> 1) * 32 + (l & 7) * 4;   // 4 slices of 32 pts
    const int c0 = (w & 1) * 48 + (l >> 3) * 12;  // 2 col halves, 4 col groups

    const int base0 = blockIdx.x * 256;
#pragma unroll 1
    for (int pass = 0; pass < 2; pass++) {
        const int base = base0 + pass * 128;

        for (int idx = t; idx < 128 * 67; idx += 256) {
            int p = idx / 67, i = idx % 67;
            int pt = base + p;
            float v = 0.0f;
            if (pt < N0C)
                v = (i < 64) ? feats0[(size_t)pt * 64 + i]
                             : coords0[(size_t)pt * 3 + (i - 64)];
            Xs[i][p] = v;
        }
        __syncthreads();

        unsigned long long acc[4][6];
#pragma unroll
        for (int m = 0; m < 6; m++) {
            unsigned long long b = pack2(Bs[c0 + 2 * m], Bs[c0 + 2 * m + 1]);
#pragma unroll
            for (int pp = 0; pp < 4; pp++) acc[pp][m] = b;
        }

#pragma unroll 4
        for (int i = 0; i < 67; i++) {
            const float4 xv = *(const float4*)&Xs[i][p0];
            const unsigned long long* wr = (const unsigned long long*)&Ws[i][c0];
            const unsigned long long w0 = wr[0], w1 = wr[1], w2 = wr[2];
            const unsigned long long w3 = wr[3], w4 = wr[4], w5 = wr[5];
            unsigned long long xx[4];
            xx[0] = pack2(xv.x, xv.x); xx[1] = pack2(xv.y, xv.y);
            xx[2] = pack2(xv.z, xv.z); xx[3] = pack2(xv.w, xv.w);
#pragma unroll
            for (int pp = 0; pp < 4; pp++) {
                FFMA2(acc[pp][0], xx[pp], w0, acc[pp][0]);
                FFMA2(acc[pp][1], xx[pp], w1, acc[pp][1]);
                FFMA2(acc[pp][2], xx[pp], w2, acc[pp][2]);
                FFMA2(acc[pp][3], xx[pp], w3, acc[pp][3]);
                FFMA2(acc[pp][4], xx[pp], w4, acc[pp][4]);
                FFMA2(acc[pp][5], xx[pp], w5, acc[pp][5]);
            }
        }

#pragma unroll
        for (int pp = 0; pp < 4; pp++) {
            int pt = base + p0 + pp;
            if (pt < N0C) {
                __half* row = g_KVh + (size_t)pt * 128;
#pragma unroll
                for (int m = 0; m < 6; m++) {
                    int c = c0 + 2 * m;                 // pair never straddles c=32
                    int hidx = (c < 32) ? c : c + 32;   // V shifted to half-idx 64+
                    float2 v = unpack2(acc[pp][m]);
                    *(__half2*)(row + hidx) = __floats2half2_rn(v.x, v.y);
                }
            }
        }
        __syncthreads();
    }
}

// ---------------------------------------------------------------------------
// Attention: ONE warp per query, 8 queries per 256-thread block. (Unchanged.)
// ---------------------------------------------------------------------------
__global__ __launch_bounds__(256) void attn_kernel(
    const float* __restrict__ coords1,
    const int*   __restrict__ knn,
    const float* __restrict__ Wv,
    float*       __restrict__ out)
{
    const int l = threadIdx.x & 31;
    const int n = blockIdx.x * 8 + (threadIdx.x >> 5);  // N1C % 8 == 0

    int myidx = 0;
    if (l < 16) myidx = knn[(size_t)n * 16 + l];

    const int h    = l & 3;
    const int rsub = l >> 2;

    const float4 q0 = *(const float4*)(g_Q + (size_t)n * 32 + h * 8);
    const float4 q1 = *(const float4*)(g_Q + (size_t)n * 32 + h * 8 + 4);

    const int j0 = __shfl_sync(0xffffffffu, myidx, rsub);
    const int j1 = __shfl_sync(0xffffffffu, myidx, 8 + rsub);

    const uint4 kc0 = *(const uint4*)(g_KVh + (size_t)j0 * 128 + h * 8);
    const uint4 kc1 = *(const uint4*)(g_KVh + (size_t)j1 * 128 + h * 8);

    float logit0, logit1;
    {
        const __half2* kh = (const __half2*)&kc0;
        float2 a = __half22float2(kh[0]), b = __half22float2(kh[1]);
        float2 c = __half22float2(kh[2]), d = __half22float2(kh[3]);
        logit0 = a.x * q0.x + a.y * q0.y + b.x * q0.z + b.y * q0.w
               + c.x * q1.x + c.y * q1.y + d.x * q1.z + d.y * q1.w;
    }
    {
        const __half2* kh = (const __half2*)&kc1;
        float2 a = __half22float2(kh[0]), b = __half22float2(kh[1]);
        float2 c = __half22float2(kh[2]), d = __half22float2(kh[3]);
        logit1 = a.x * q0.x + a.y * q0.y + b.x * q0.z + b.y * q0.w
               + c.x * q1.x + c.y * q1.y + d.x * q1.z + d.y * q1.w;
    }
    logit0 *= 0.35355339059327373f;
    logit1 *= 0.35355339059327373f;

    float m = fmaxf(logit0, logit1);
    m = fmaxf(m, __shfl_xor_sync(0xffffffffu, m, 4));
    m = fmaxf(m, __shfl_xor_sync(0xffffffffu, m, 8));
    m = fmaxf(m, __shfl_xor_sync(0xffffffffu, m, 16));
    float e0 = __expf(logit0 - m);
    float e1 = __expf(logit1 - m);
    float s = e0 + e1;
    s += __shfl_xor_sync(0xffffffffu, s, 4);
    s += __shfl_xor_sync(0xffffffffu, s, 8);
    s += __shfl_xor_sync(0xffffffffu, s, 16);
    const float inv_s = __frcp_rn(s);
    const float a0 = e0 * inv_s;
    const float a1 = e1 * inv_s;

    const int hd = l >> 3;
    float accx = 0.0f, accy = 0.0f;
#pragma unroll
    for (int r = 0; r < 16; r++) {
        const int jr = __shfl_sync(0xffffffffu, myidx, r);
        const int src = ((r & 7) << 2) + hd;
        const float ar = __shfl_sync(0xffffffffu, (r < 8) ? a0 : a1, src);
        const __half2 v = *(const __half2*)(g_KVh + (size_t)jr * 128 + 64 + 2 * l);
        const float2 vf = __half22float2(v);
        accx = fmaf(ar, vf.x, accx);
        accy = fmaf(ar, vf.y, accy);
    }

    const float c1x = coords1[(size_t)n * 3 + 0];
    const float c1y = coords1[(size_t)n * 3 + 1];
    const float c1z = coords1[(size_t)n * 3 + 2];
    const float2 wv0 = *(const float2*)(Wv + (size_t)64 * 64 + 2 * l);
    const float2 wv1 = *(const float2*)(Wv + (size_t)65 * 64 + 2 * l);
    const float2 wv2 = *(const float2*)(Wv + (size_t)66 * 64 + 2 * l);
    const float cvx = c1x * wv0.x + c1y * wv1.x + c1z * wv2.x;
    const float cvy = c1x * wv0.y + c1y * wv1.y + c1z * wv2.y;

    *(float2*)(out + (size_t)n * 64 + 2 * l) = make_float2(accx - cvx, accy - cvy);
}

// ---------------------------------------------------------------------------
// knn passthrough (int -> float), int4/float4 vectorized.
// ---------------------------------------------------------------------------
__global__ void idx_copy(const int* __restrict__ knn, float* __restrict__ out, int n)
{
    int n4 = n >> 2;
    int i = blockIdx.x * blockDim.x + threadIdx.x;
    if (i < n4) {
        int4 v = ((const int4*)knn)[i];
        ((float4*)out)[i] = make_float4((float)v.x, (float)v.y, (float)v.z, (float)v.w);
    }
    if (i == 0)
        for (int r = n4 * 4; r < n; r++) out[r] = (float)knn[r];
}

extern "C" void kernel_launch(void* const* d_in, const int* in_sizes, int n_in,
                              void* d_out, int out_size)
{
    const float* coords0 = (const float*)d_in[0];
    const float* coords1 = (const float*)d_in[1];
    const float* feats0  = (const float*)d_in[2];
    const float* feats1  = (const float*)d_in[3];
    const int*   knn     = (const int*)  d_in[4];
    const float* Wq      = (const float*)d_in[5];
    const float* bq      = (const float*)d_in[6];
    const float* Wk      = (const float*)d_in[7];
    const float* bk      = (const float*)d_in[8];
    const float* Wv      = (const float*)d_in[9];
    const float* bv      = (const float*)d_in[10];
    float* out = (float*)d_out;

    static_assert(KV_SMEM_FLOATS * 4 < 227 * 1024, "kv smem");
    cudaFuncSetAttribute(kv_prep, cudaFuncAttributeMaxDynamicSharedMemorySize,
                         KV_SMEM_FLOATS * 4);

    // Order matters for ncu -s 5: (q0, kv1, attn2, idx3, q4, kv5) -> profiles kv_prep.
    q_prep<<<Q_BLOCKS, 256>>>(feats1, Wq, bq);
    kv_prep<<<KV_BLOCKS, 256, KV_SMEM_FLOATS * 4>>>(feats0, coords0, Wk, bk, Wv, bv);
    attn_kernel<<<N1C / 8, 256>>>(coords1, knn, Wv, out);

    int tail = out_size - N1C * 64;
    if (tail > 0) {
        int n4 = tail >> 2;
        int blocks = (n4 + 255) / 256;
        if (blocks < 1) blocks = 1;
        idx_copy<<<blocks, 256>>>(knn, out + (size_t)N1C * 64, tail);
    }
}

// round 15
// speedup vs baseline: 1.2612x; 1.2612x over previous
#include <cuda_runtime.h>
#include <cuda_fp16.h>

#define N0C 100000
#define N1C 100000

#define KV_BLOCKS ((N0C + 255) / 256)   // 391
#define Q_BLOCKS  ((N1C + 255) / 256)   // 391

// Packed-f32x2 helpers (Blackwell FFMA2 path, PTX-only)
#define FFMA2(d, a, b, c) \
    asm("fma.rn.f32x2 %0, %1, %2, %3;" : "=l"(d) : "l"(a), "l"(b), "l"(c))
__device__ __forceinline__ unsigned long long pack2(float lo, float hi) {
    unsigned long long r;
    asm("mov.b64 %0, {%1, %2};" : "=l"(r) : "f"(lo), "f"(hi));
    return r;
}
__device__ __forceinline__ float2 unpack2(unsigned long long v) {
    float2 r;
    asm("mov.b64 {%0, %1}, %2;" : "=f"(r.x), "=f"(r.y) : "l"(v));
    return r;
}

// KV0 in fp16, padded rows of 128 halves (256B, line-aligned):
//   halves [0,32)   : K part  (feats0@Wk[0:64] + coords0@Wk[64:67] + bk)
//   halves [64,128) : V part  (feats0@Wv[0:64] + coords0@Wv[64:67] + bv)
__device__ __half g_KVh[(size_t)N0C * 128];
__device__ float  g_Q[(size_t)N1C * 32];

// ---------------------------------------------------------------------------
// Fused prep kernel. Blocks [0,391): KV GEMM (256 rows each, 4 sub-tiles);
// blocks [391,782): Q GEMM (256 rows each); rest: idx passthrough.
// ---------------------------------------------------------------------------
__global__ __launch_bounds__(256) void prep_kernel(
    const float* __restrict__ feats0, const float* __restrict__ coords0,
    const float* __restrict__ Wk, const float* __restrict__ bk,
    const float* __restrict__ Wv, const float* __restrict__ bv,
    const float* __restrict__ feats1,
    const float* __restrict__ Wq, const float* __restrict__ bq,
    const int*   __restrict__ knn, float* __restrict__ outTail, int tailN)
{
    // Ws(67*96) + Bs(96) + Xs(67*68) = 11084 floats = 44.3 KB.
    __shared__ __align__(16) float smem[67 * 96 + 96 + 67 * 68];
    const int t = threadIdx.x;

    if (blockIdx.x < KV_BLOCKS) {
        // ---------------- KV0: [256 pts, 67 in] x [67, 96 out] ----------------
        float (*Ws)[96] = (float (*)[96])smem;                   // weights [i][c]
        float* Bs       = smem + 67 * 96;                        // bias [96]
        float (*Xs)[68] = (float (*)[68])(smem + 67 * 96 + 96);  // inputs [i][p], i<67

        // Stage weights ONCE per 256 rows (float4).
        const float4* Wk4 = (const float4*)Wk;   // 67 x 8
        const float4* Wv4 = (const float4*)Wv;   // 67 x 16
        for (int idx = t; idx < 67 * 24; idx += 256) {
            int i = idx / 24, c4 = idx % 24;
            float4 v = (c4 < 8) ? Wk4[i * 8 + c4] : Wv4[i * 16 + (c4 - 8)];
            *(float4*)&Ws[i][c4 * 4] = v;
        }
        if (t < 96) Bs[t] = (t < 32) ? bk[t] : bv[t - 32];

        // Thread tile: 2 points x 12 cols. Warp = 8 pts x 96 cols.
        // Weights via 3x LDS.128 (c0 = 12*colg -> 48B-aligned, bank-clean),
        // x via LDS.64 broadcast.
        const int colg = t & 7;          // 8 col groups of 12
        const int ptg  = t >> 3;         // 32 point groups of 2
        const int c0 = colg * 12;
        const int p0 = ptg * 2;
        const int base0 = blockIdx.x * 256;

#pragma unroll 1
        for (int sub = 0; sub < 4; sub++) {
            const int base = base0 + sub * 64;

            // Stage X transposed [i][p] (i fastest in gmem -> coalesced).
            for (int idx = t; idx < 64 * 67; idx += 256) {
                int p = idx / 67, i = idx % 67;
                int pt = base + p;
                float v = 0.0f;
                if (pt < N0C)
                    v = (i < 64) ? feats0[(size_t)pt * 64 + i]
                                 : coords0[(size_t)pt * 3 + (i - 64)];
                Xs[i][p] = v;
            }
            __syncthreads();

            unsigned long long acc2[2][6];
#pragma unroll
            for (int m = 0; m < 6; m++) {
                unsigned long long b = pack2(Bs[c0 + 2 * m], Bs[c0 + 2 * m + 1]);
                acc2[0][m] = b;
                acc2[1][m] = b;
            }

#pragma unroll 4
            for (int i = 0; i < 67; i++) {
                const float2 xv = *(const float2*)&Xs[i][p0];
                const ulonglong2* wr = (const ulonglong2*)&Ws[i][c0];
                const ulonglong2 wa = wr[0];   // LDS.128: cols c0..c0+3
                const ulonglong2 wb = wr[1];   // cols c0+4..c0+7
                const ulonglong2 wc = wr[2];   // cols c0+8..c0+11
                const unsigned long long x0 = pack2(xv.x, xv.x);
                const unsigned long long x1 = pack2(xv.y, xv.y);
                FFMA2(acc2[0][0], x0, wa.x, acc2[0][0]);
                FFMA2(acc2[0][1], x0, wa.y, acc2[0][1]);
                FFMA2(acc2[0][2], x0, wb.x, acc2[0][2]);
                FFMA2(acc2[0][3], x0, wb.y, acc2[0][3]);
                FFMA2(acc2[0][4], x0, wc.x, acc2[0][4]);
                FFMA2(acc2[0][5], x0, wc.y, acc2[0][5]);
                FFMA2(acc2[1][0], x1, wa.x, acc2[1][0]);
                FFMA2(acc2[1][1], x1, wa.y, acc2[1][1]);
                FFMA2(acc2[1][2], x1, wb.x, acc2[1][2]);
                FFMA2(acc2[1][3], x1, wb.y, acc2[1][3]);
                FFMA2(acc2[1][4], x1, wc.x, acc2[1][4]);
                FFMA2(acc2[1][5], x1, wc.y, acc2[1][5]);
            }

#pragma unroll
            for (int pp = 0; pp < 2; pp++) {
                int pt = base + p0 + pp;
                if (pt < N0C) {
                    __half* row = g_KVh + (size_t)pt * 128;
#pragma unroll
                    for (int m = 0; m < 6; m++) {
                        int c = c0 + 2 * m;                 // pair never straddles c=32
                        int hidx = (c < 32) ? c : c + 32;   // V shifted to half-idx 64+
                        float2 v = unpack2(acc2[pp][m]);
                        *(__half2*)(row + hidx) = __floats2half2_rn(v.x, v.y);
                    }
                }
            }
            __syncthreads();
        }
    } else if (blockIdx.x < KV_BLOCKS + Q_BLOCKS) {
        // ---------------- Q: [256 pts, 64 in] x [64, 32 out] ----------------
        float (*Ws)[32] = (float (*)[32])smem;                   // [64][32]
        float* Bs       = smem + 64 * 32;                        // [32]
        float (*Xs)[68] = (float (*)[68])(smem + 64 * 32 + 32);  // [i][p], i<64

        // Flat float4 copy of the 64x32 weight tile.
        const float4* Wq4 = (const float4*)Wq;
        for (int idx = t; idx < 512; idx += 256)
            ((float4*)Ws)[idx] = Wq4[idx];
        if (t < 32) Bs[t] = bq[t];

        const int tc = t & 15;
        const int tp = t >> 4;
        const int c0 = tc * 2;          // even
        const int p0 = tp * 4;
        const int base0 = (blockIdx.x - KV_BLOCKS) * 256;

#pragma unroll 1
        for (int sub = 0; sub < 4; sub++) {
            const int base = base0 + sub * 64;

            for (int idx = t; idx < 64 * 64; idx += 256) {
                int p = idx >> 6, i = idx & 63;
                int pt = base + p;
                Xs[i][p] = (pt < N1C) ? feats1[(size_t)pt * 64 + i] : 0.0f;
            }
            __syncthreads();

            unsigned long long acc2[4];
            {
                unsigned long long b = pack2(Bs[c0], Bs[c0 + 1]);
#pragma unroll
                for (int pp = 0; pp < 4; pp++) acc2[pp] = b;
            }

#pragma unroll 8
            for (int i = 0; i < 64; i++) {
                const float4 xv = *(const float4*)&Xs[i][p0];
                const unsigned long long w = *(const unsigned long long*)&Ws[i][c0];
                unsigned long long xx[4];
                xx[0] = pack2(xv.x, xv.x); xx[1] = pack2(xv.y, xv.y);
                xx[2] = pack2(xv.z, xv.z); xx[3] = pack2(xv.w, xv.w);
#pragma unroll
                for (int pp = 0; pp < 4; pp++)
                    FFMA2(acc2[pp], xx[pp], w, acc2[pp]);
            }

#pragma unroll
            for (int pp = 0; pp < 4; pp++) {
                int pt = base + p0 + pp;
                if (pt < N1C) {
                    float2 v = unpack2(acc2[pp]);
                    *(float2*)(g_Q + (size_t)pt * 32 + c0) = v;
                }
            }
            __syncthreads();
        }
    } else {
        // ---------------- knn_idxs passthrough (int -> float) ----------------
        int b = blockIdx.x - KV_BLOCKS - Q_BLOCKS;
        int stride = (gridDim.x - KV_BLOCKS - Q_BLOCKS) * 256;
        for (int i = b * 256 + t; i < tailN; i += stride)
            outTail[i] = (float)knn[i];
    }
}

// ---------------------------------------------------------------------------
// Attention: ONE warp per query, 8 queries per 256-thread block. (Unchanged:
// ~40us, MIO/L1-wavefront bound near its floor for this layout.)
// ---------------------------------------------------------------------------
__global__ __launch_bounds__(256) void attn_kernel(
    const float* __restrict__ coords1,
    const int*   __restrict__ knn,
    const float* __restrict__ Wv,
    float*       __restrict__ out)
{
    const int l = threadIdx.x & 31;
    const int n = blockIdx.x * 8 + (threadIdx.x >> 5);  // N1C % 8 == 0

    int myidx = 0;
    if (l < 16) myidx = knn[(size_t)n * 16 + l];

    const int h    = l & 3;        // head for phase A
    const int rsub = l >> 2;       // row sub-index (0..7)

    const float4 q0 = *(const float4*)(g_Q + (size_t)n * 32 + h * 8);
    const float4 q1 = *(const float4*)(g_Q + (size_t)n * 32 + h * 8 + 4);

    const int j0 = __shfl_sync(0xffffffffu, myidx, rsub);
    const int j1 = __shfl_sync(0xffffffffu, myidx, 8 + rsub);

    const uint4 kc0 = *(const uint4*)(g_KVh + (size_t)j0 * 128 + h * 8);
    const uint4 kc1 = *(const uint4*)(g_KVh + (size_t)j1 * 128 + h * 8);

    float logit0, logit1;
    {
        const __half2* kh = (const __half2*)&kc0;
        float2 a = __half22float2(kh[0]), b = __half22float2(kh[1]);
        float2 c = __half22float2(kh[2]), d = __half22float2(kh[3]);
        logit0 = a.x * q0.x + a.y * q0.y + b.x * q0.z + b.y * q0.w
               + c.x * q1.x + c.y * q1.y + d.x * q1.z + d.y * q1.w;
    }
    {
        const __half2* kh = (const __half2*)&kc1;
        float2 a = __half22float2(kh[0]), b = __half22float2(kh[1]);
        float2 c = __half22float2(kh[2]), d = __half22float2(kh[3]);
        logit1 = a.x * q0.x + a.y * q0.y + b.x * q0.z + b.y * q0.w
               + c.x * q1.x + c.y * q1.y + d.x * q1.z + d.y * q1.w;
    }
    logit0 *= 0.35355339059327373f;
    logit1 *= 0.35355339059327373f;

    // softmax across 16 rows of this head: lanes {h, h+4, ..., h+28} x 2 regs
    float m = fmaxf(logit0, logit1);
    m = fmaxf(m, __shfl_xor_sync(0xffffffffu, m, 4));
    m = fmaxf(m, __shfl_xor_sync(0xffffffffu, m, 8));
    m = fmaxf(m, __shfl_xor_sync(0xffffffffu, m, 16));
    float e0 = __expf(logit0 - m);
    float e1 = __expf(logit1 - m);
    float s = e0 + e1;
    s += __shfl_xor_sync(0xffffffffu, s, 4);
    s += __shfl_xor_sync(0xffffffffu, s, 8);
    s += __shfl_xor_sync(0xffffffffu, s, 16);
    const float inv_s = __frcp_rn(s);
    const float a0 = e0 * inv_s;
    const float a1 = e1 * inv_s;

    // Phase B: lane owns output dims (2l, 2l+1); head of those dims = l>>3.
    const int hd = l >> 3;
    float accx = 0.0f, accy = 0.0f;
#pragma unroll
    for (int r = 0; r < 16; r++) {
        const int jr = __shfl_sync(0xffffffffu, myidx, r);
        const int src = ((r & 7) << 2) + hd;
        const float ar = __shfl_sync(0xffffffffu, (r < 8) ? a0 : a1, src);
        const __half2 v = *(const __half2*)(g_KVh + (size_t)jr * 128 + 64 + 2 * l);
        const float2 vf = __half22float2(v);
        accx = fmaf(ar, vf.x, accx);
        accy = fmaf(ar, vf.y, accy);
    }

    const float c1x = coords1[(size_t)n * 3 + 0];
    const float c1y = coords1[(size_t)n * 3 + 1];
    const float c1z = coords1[(size_t)n * 3 + 2];
    const float2 wv0 = *(const float2*)(Wv + (size_t)64 * 64 + 2 * l);
    const float2 wv1 = *(const float2*)(Wv + (size_t)65 * 64 + 2 * l);
    const float2 wv2 = *(const float2*)(Wv + (size_t)66 * 64 + 2 * l);
    const float cvx = c1x * wv0.x + c1y * wv1.x + c1z * wv2.x;
    const float cvy = c1x * wv0.y + c1y * wv1.y + c1z * wv2.y;

    *(float2*)(out + (size_t)n * 64 + 2 * l) = make_float2(accx - cvx, accy - cvy);
}

extern "C" void kernel_launch(void* const* d_in, const int* in_sizes, int n_in,
                              void* d_out, int out_size)
{
    const float* coords0 = (const float*)d_in[0];
    const float* coords1 = (const float*)d_in[1];
    const float* feats0  = (const float*)d_in[2];
    const float* feats1  = (const float*)d_in[3];
    const int*   knn     = (const int*)  d_in[4];
    const float* Wq      = (const float*)d_in[5];
    const float* bq      = (const float*)d_in[6];
    const float* Wk      = (const float*)d_in[7];
    const float* bk      = (const float*)d_in[8];
    const float* Wv      = (const float*)d_in[9];
    const float* bv      = (const float*)d_in[10];
    float* out = (float*)d_out;

    int tail = out_size - N1C * 64;
    if (tail < 0) tail = 0;
    int copyBlocks = tail > 0 ? (tail + 1023) / 1024 : 0;

    prep_kernel<<<KV_BLOCKS + Q_BLOCKS + copyBlocks, 256>>>(
        feats0, coords0, Wk, bk, Wv, bv,
        feats1, Wq, bq,
        knn, out + (size_t)N1C * 64, tail);

    attn_kernel<<<N1C / 8, 256>>>(coords1, knn, Wv, out);
}

// round 16
// speedup vs baseline: 1.5270x; 1.2107x over previous
#include <cuda_runtime.h>
#include <cuda_fp16.h>

#define N0C 100000
#define N1C 100000

#define KV_BLOCKS ((N0C + 255) / 256)   // 391
#define Q_BLOCKS  ((N1C + 255) / 256)   // 391

// Packed-f32x2 helpers (Blackwell FFMA2 path, PTX-only)
#define FFMA2(d, a, b, c) \
    asm("fma.rn.f32x2 %0, %1, %2, %3;" : "=l"(d) : "l"(a), "l"(b), "l"(c))
__device__ __forceinline__ unsigned long long pack2(float lo, float hi) {
    unsigned long long r;
    asm("mov.b64 %0, {%1, %2};" : "=l"(r) : "f"(lo), "f"(hi));
    return r;
}
__device__ __forceinline__ float2 unpack2(unsigned long long v) {
    float2 r;
    asm("mov.b64 {%0, %1}, %2;" : "=f"(r.x), "=f"(r.y) : "l"(v));
    return r;
}

// KV0 in fp16, padded rows of 128 halves (256B, line-aligned):
//   halves [0,32)   : K part  (feats0@Wk[0:64] + coords0@Wk[64:67] + bk)
//   halves [64,128) : V part  (feats0@Wv[0:64] + coords0@Wv[64:67] + bv)
__device__ __half g_KVh[(size_t)N0C * 128];
__device__ float  g_Q[(size_t)N1C * 32];

// ---------------------------------------------------------------------------
// Fused prep kernel (R13 config — best known). Blocks [0,391): KV GEMM
// (256 rows each, 4 sub-tiles of 64, thread tile 4pts x 6cols);
// blocks [391,782): Q GEMM.
// ---------------------------------------------------------------------------
__global__ __launch_bounds__(256) void prep_kernel(
    const float* __restrict__ feats0, const float* __restrict__ coords0,
    const float* __restrict__ Wk, const float* __restrict__ bk,
    const float* __restrict__ Wv, const float* __restrict__ bv,
    const float* __restrict__ feats1,
    const float* __restrict__ Wq, const float* __restrict__ bq)
{
    // Ws(67*96) + Bs(96) + Xs(67*68) = 11084 floats = 44.3 KB.
    __shared__ __align__(16) float smem[67 * 96 + 96 + 67 * 68];
    const int t = threadIdx.x;

    if (blockIdx.x < KV_BLOCKS) {
        // ---------------- KV0: [256 pts, 67 in] x [67, 96 out] ----------------
        float (*Ws)[96] = (float (*)[96])smem;                   // weights [i][c]
        float* Bs       = smem + 67 * 96;                        // bias [96]
        float (*Xs)[68] = (float (*)[68])(smem + 67 * 96 + 96);  // inputs [i][p], i<67

        // Stage weights ONCE per 256 rows (float4).
        const float4* Wk4 = (const float4*)Wk;   // 67 x 8
        const float4* Wv4 = (const float4*)Wv;   // 67 x 16
        for (int idx = t; idx < 67 * 24; idx += 256) {
            int i = idx / 24, c4 = idx % 24;
            float4 v = (c4 < 8) ? Wk4[i * 8 + c4] : Wv4[i * 16 + (c4 - 8)];
            *(float4*)&Ws[i][c4 * 4] = v;
        }
        if (t < 96) Bs[t] = (t < 32) ? bk[t] : bv[t - 32];

        const int tc = t & 15;
        const int tp = t >> 4;
        const int c0 = tc * 6;          // even
        const int p0 = tp * 4;
        const int base0 = blockIdx.x * 256;

#pragma unroll 1
        for (int sub = 0; sub < 4; sub++) {
            const int base = base0 + sub * 64;

            // Stage X transposed [i][p] (i fastest in gmem -> coalesced).
            for (int idx = t; idx < 64 * 67; idx += 256) {
                int p = idx / 67, i = idx % 67;
                int pt = base + p;
                float v = 0.0f;
                if (pt < N0C)
                    v = (i < 64) ? feats0[(size_t)pt * 64 + i]
                                 : coords0[(size_t)pt * 3 + (i - 64)];
                Xs[i][p] = v;
            }
            __syncthreads();

            unsigned long long acc2[4][3];
#pragma unroll
            for (int m = 0; m < 3; m++) {
                unsigned long long b = pack2(Bs[c0 + 2 * m], Bs[c0 + 2 * m + 1]);
#pragma unroll
                for (int pp = 0; pp < 4; pp++) acc2[pp][m] = b;
            }

#pragma unroll 4
            for (int i = 0; i < 67; i++) {
                const float4 xv = *(const float4*)&Xs[i][p0];
                const unsigned long long* wrow = (const unsigned long long*)&Ws[i][c0];
                const unsigned long long w0 = wrow[0], w1 = wrow[1], w2 = wrow[2];
                unsigned long long xx[4];
                xx[0] = pack2(xv.x, xv.x); xx[1] = pack2(xv.y, xv.y);
                xx[2] = pack2(xv.z, xv.z); xx[3] = pack2(xv.w, xv.w);
#pragma unroll
                for (int pp = 0; pp < 4; pp++) {
                    FFMA2(acc2[pp][0], xx[pp], w0, acc2[pp][0]);
                    FFMA2(acc2[pp][1], xx[pp], w1, acc2[pp][1]);
                    FFMA2(acc2[pp][2], xx[pp], w2, acc2[pp][2]);
                }
            }

#pragma unroll
            for (int pp = 0; pp < 4; pp++) {
                int pt = base + p0 + pp;
                if (pt < N0C) {
                    __half* row = g_KVh + (size_t)pt * 128;
#pragma unroll
                    for (int m = 0; m < 3; m++) {
                        int c = c0 + 2 * m;                 // pair never straddles c=32
                        int hidx = (c < 32) ? c : c + 32;   // V shifted to half-idx 64+
                        float2 v = unpack2(acc2[pp][m]);
                        *(__half2*)(row + hidx) = __floats2half2_rn(v.x, v.y);
                    }
                }
            }
            __syncthreads();
        }
    } else {
        // ---------------- Q: [256 pts, 64 in] x [64, 32 out] ----------------
        float (*Ws)[32] = (float (*)[32])smem;                   // [64][32]
        float* Bs       = smem + 64 * 32;                        // [32]
        float (*Xs)[68] = (float (*)[68])(smem + 64 * 32 + 32);  // [i][p], i<64

        // Flat float4 copy of the 64x32 weight tile.
        const float4* Wq4 = (const float4*)Wq;
        for (int idx = t; idx < 512; idx += 256)
            ((float4*)Ws)[idx] = Wq4[idx];
        if (t < 32) Bs[t] = bq[t];

        const int tc = t & 15;
        const int tp = t >> 4;
        const int c0 = tc * 2;          // even
        const int p0 = tp * 4;
        const int base0 = (blockIdx.x - KV_BLOCKS) * 256;

#pragma unroll 1
        for (int sub = 0; sub < 4; sub++) {
            const int base = base0 + sub * 64;

            for (int idx = t; idx < 64 * 64; idx += 256) {
                int p = idx >> 6, i = idx & 63;
                int pt = base + p;
                Xs[i][p] = (pt < N1C) ? feats1[(size_t)pt * 64 + i] : 0.0f;
            }
            __syncthreads();

            unsigned long long acc2[4];
            {
                unsigned long long b = pack2(Bs[c0], Bs[c0 + 1]);
#pragma unroll
                for (int pp = 0; pp < 4; pp++) acc2[pp] = b;
            }

#pragma unroll 8
            for (int i = 0; i < 64; i++) {
                const float4 xv = *(const float4*)&Xs[i][p0];
                const unsigned long long w = *(const unsigned long long*)&Ws[i][c0];
                unsigned long long xx[4];
                xx[0] = pack2(xv.x, xv.x); xx[1] = pack2(xv.y, xv.y);
                xx[2] = pack2(xv.z, xv.z); xx[3] = pack2(xv.w, xv.w);
#pragma unroll
                for (int pp = 0; pp < 4; pp++)
                    FFMA2(acc2[pp], xx[pp], w, acc2[pp]);
            }

#pragma unroll
            for (int pp = 0; pp < 4; pp++) {
                int pt = base + p0 + pp;
                if (pt < N1C) {
                    float2 v = unpack2(acc2[pp]);
                    *(float2*)(g_Q + (size_t)pt * 32 + c0) = v;
                }
            }
            __syncthreads();
        }
    }
}

// ---------------------------------------------------------------------------
// Attention: ONE warp per query, 8 queries per 256-thread block. (Unchanged:
// ~40us, MIO/L1-wavefront bound near its floor for this layout.)
// ---------------------------------------------------------------------------
__global__ __launch_bounds__(256) void attn_kernel(
    const float* __restrict__ coords1,
    const int*   __restrict__ knn,
    const float* __restrict__ Wv,
    float*       __restrict__ out)
{
    const int l = threadIdx.x & 31;
    const int n = blockIdx.x * 8 + (threadIdx.x >> 5);  // N1C % 8 == 0

    int myidx = 0;
    if (l < 16) myidx = knn[(size_t)n * 16 + l];

    const int h    = l & 3;        // head for phase A
    const int rsub = l >> 2;       // row sub-index (0..7)

    const float4 q0 = *(const float4*)(g_Q + (size_t)n * 32 + h * 8);
    const float4 q1 = *(const float4*)(g_Q + (size_t)n * 32 + h * 8 + 4);

    const int j0 = __shfl_sync(0xffffffffu, myidx, rsub);
    const int j1 = __shfl_sync(0xffffffffu, myidx, 8 + rsub);

    const uint4 kc0 = *(const uint4*)(g_KVh + (size_t)j0 * 128 + h * 8);
    const uint4 kc1 = *(const uint4*)(g_KVh + (size_t)j1 * 128 + h * 8);

    float logit0, logit1;
    {
        const __half2* kh = (const __half2*)&kc0;
        float2 a = __half22float2(kh[0]), b = __half22float2(kh[1]);
        float2 c = __half22float2(kh[2]), d = __half22float2(kh[3]);
        logit0 = a.x * q0.x + a.y * q0.y + b.x * q0.z + b.y * q0.w
               + c.x * q1.x + c.y * q1.y + d.x * q1.z + d.y * q1.w;
    }
    {
        const __half2* kh = (const __half2*)&kc1;
        float2 a = __half22float2(kh[0]), b = __half22float2(kh[1]);
        float2 c = __half22float2(kh[2]), d = __half22float2(kh[3]);
        logit1 = a.x * q0.x + a.y * q0.y + b.x * q0.z + b.y * q0.w
               + c.x * q1.x + c.y * q1.y + d.x * q1.z + d.y * q1.w;
    }
    logit0 *= 0.35355339059327373f;
    logit1 *= 0.35355339059327373f;

    // softmax across 16 rows of this head: lanes {h, h+4, ..., h+28} x 2 regs
    float m = fmaxf(logit0, logit1);
    m = fmaxf(m, __shfl_xor_sync(0xffffffffu, m, 4));
    m = fmaxf(m, __shfl_xor_sync(0xffffffffu, m, 8));
    m = fmaxf(m, __shfl_xor_sync(0xffffffffu, m, 16));
    float e0 = __expf(logit0 - m);
    float e1 = __expf(logit1 - m);
    float s = e0 + e1;
    s += __shfl_xor_sync(0xffffffffu, s, 4);
    s += __shfl_xor_sync(0xffffffffu, s, 8);
    s += __shfl_xor_sync(0xffffffffu, s, 16);
    const float inv_s = __frcp_rn(s);
    const float a0 = e0 * inv_s;
    const float a1 = e1 * inv_s;

    // Phase B: lane owns output dims (2l, 2l+1); head of those dims = l>>3.
    const int hd = l >> 3;
    float accx = 0.0f, accy = 0.0f;
#pragma unroll
    for (int r = 0; r < 16; r++) {
        const int jr = __shfl_sync(0xffffffffu, myidx, r);
        const int src = ((r & 7) << 2) + hd;
        const float ar = __shfl_sync(0xffffffffu, (r < 8) ? a0 : a1, src);
        const __half2 v = *(const __half2*)(g_KVh + (size_t)jr * 128 + 64 + 2 * l);
        const float2 vf = __half22float2(v);
        accx = fmaf(ar, vf.x, accx);
        accy = fmaf(ar, vf.y, accy);
    }

    const float c1x = coords1[(size_t)n * 3 + 0];
    const float c1y = coords1[(size_t)n * 3 + 1];
    const float c1z = coords1[(size_t)n * 3 + 2];
    const float2 wv0 = *(const float2*)(Wv + (size_t)64 * 64 + 2 * l);
    const float2 wv1 = *(const float2*)(Wv + (size_t)65 * 64 + 2 * l);
    const float2 wv2 = *(const float2*)(Wv + (size_t)66 * 64 + 2 * l);
    const float cvx = c1x * wv0.x + c1y * wv1.x + c1z * wv2.x;
    const float cvy = c1x * wv0.y + c1y * wv1.y + c1z * wv2.y;

    *(float2*)(out + (size_t)n * 64 + 2 * l) = make_float2(accx - cvx, accy - cvy);
}

// ---------------------------------------------------------------------------
// knn passthrough (int -> float), separate launch #2 so the ncu window
// (harness pre-launches + skip 5) lands on prep_kernel (launch 3 mod 3 == 0).
// ---------------------------------------------------------------------------
__global__ void idx_copy(const int* __restrict__ knn, float* __restrict__ out, int n)
{
    int n4 = n >> 2;
    int i = blockIdx.x * blockDim.x + threadIdx.x;
    if (i < n4) {
        int4 v = ((const int4*)knn)[i];
        ((float4*)out)[i] = make_float4((float)v.x, (float)v.y, (float)v.z, (float)v.w);
    }
    if (i == 0)
        for (int r = n4 * 4; r < n; r++) out[r] = (float)knn[r];
}

extern "C" void kernel_launch(void* const* d_in, const int* in_sizes, int n_in,
                              void* d_out, int out_size)
{
    const float* coords0 = (const float*)d_in[0];
    const float* coords1 = (const float*)d_in[1];
    const float* feats0  = (const float*)d_in[2];
    const float* feats1  = (const float*)d_in[3];
    const int*   knn     = (const int*)  d_in[4];
    const float* Wq      = (const float*)d_in[5];
    const float* bq      = (const float*)d_in[6];
    const float* Wk      = (const float*)d_in[7];
    const float* bk      = (const float*)d_in[8];
    const float* Wv      = (const float*)d_in[9];
    const float* bv      = (const float*)d_in[10];
    float* out = (float*)d_out;

    prep_kernel<<<KV_BLOCKS + Q_BLOCKS, 256>>>(
        feats0, coords0, Wk, bk, Wv, bv, feats1, Wq, bq);

    attn_kernel<<<N1C / 8, 256>>>(coords1, knn, Wv, out);

    int tail = out_size - N1C * 64;
    if (tail > 0) {
        int n4 = tail >> 2;
        int blocks = (n4 + 255) / 256;
        if (blocks < 1) blocks = 1;
        idx_copy<<<blocks, 256>>>(knn, out + (size_t)N1C * 64, tail);
    } else {
        // keep 3 launches/iter so the ncu skip window stays on prep_kernel
        idx_copy<<<1, 32>>>(knn, out + (size_t)N1C * 64, 0);
    }
}